// round 7
// baseline (speedup 1.0000x reference)
#include <cuda_runtime.h>
#include <cuda_fp16.h>
#include <mma.h>
#include <cstdint>

using namespace nvcuda;

#define HID   1024
#define BATCH 64
#define SEQ   256
#define NGATE 4096
#define NCTA  128
#define WHH_LD 1032
#define HA_LD 136

__device__ float  g_xg[(size_t)BATCH * SEQ * NGATE];  // [b*SEQ+t][g*HID+k] fp32
// blocked h ring (fp16): g_h[slot][kblk*512 + b*8 + kl]
__device__ __half g_h[4][BATCH * HID];
__device__ int    g_cnt8[8];                          // group g: sum of steps published by CTAs [16g,16g+16)

__device__ __forceinline__ void cp16(void* s, const void* g) {
    uint32_t sa = (uint32_t)__cvta_generic_to_shared(s);
    asm volatile("cp.async.cg.shared.global [%0], [%1], 16;\n" :: "r"(sa), "l"(g));
}
__device__ __forceinline__ void cp_commit() { asm volatile("cp.async.commit_group;\n"); }
template<int N> __device__ __forceinline__ void cp_wait() {
    asm volatile("cp.async.wait_group %0;\n" :: "n"(N));
}
__device__ __forceinline__ float sigm(float x) { return 1.0f / (1.0f + __expf(-x)); }
__device__ __forceinline__ int ld_acq(const int* p) {
    int v;
    asm volatile("ld.acquire.gpu.global.s32 %0, [%1];" : "=r"(v) : "l"(p) : "memory");
    return v;
}

// ------------------------------------------------------------------ phase A (tf32, fp32 inputs)
#define BK 32
#define ASMEM (2 * 3 * 128 * 36 * 4)
__global__ void __launch_bounds__(256, 2) gemm_xg_kernel(const float* __restrict__ x,
                                                         const float* __restrict__ Wx) {
    extern __shared__ float sm[];
    float* As = sm;                   // [3][128][36]
    float* Bs = sm + 3 * 128 * 36;    // [3][128][36]
    const int tid = threadIdx.x;
    const int wid = tid >> 5;
    const int wm = wid & 3, wn = wid >> 2;
    const int tm = blockIdx.y * 128;
    const int tn = blockIdx.x * 128;

    if (blockIdx.x == 0 && blockIdx.y == 0 && tid < 8) g_cnt8[tid] = 0;  // reset (kernel boundary orders vs lstm)

    wmma::fragment<wmma::accumulator, 16, 16, 8, float> acc[2][4];
    #pragma unroll
    for (int i = 0; i < 2; i++)
        #pragma unroll
        for (int j = 0; j < 4; j++) wmma::fill_fragment(acc[i][j], 0.0f);

    auto issue = [&](int kt) {
        int st = kt % 3;
        int kk = kt * BK;
        float* a = As + st * 128 * 36;
        float* b = Bs + st * 128 * 36;
        #pragma unroll
        for (int i = 0; i < 4; i++) {
            int li = tid + i * 256;  // 0..1023
            int r = li >> 3, sg = li & 7;
            cp16(a + r * 36 + sg * 4, x  + (size_t)(tm + r) * HID + kk + sg * 4);
            cp16(b + r * 36 + sg * 4, Wx + (size_t)(tn + r) * HID + kk + sg * 4);
        }
    };
    issue(0); cp_commit();
    issue(1); cp_commit();

    for (int kt = 0; kt < HID / BK; kt++) {
        cp_wait<1>();
        __syncthreads();
        const int st = kt % 3;
        const float* a = As + st * 128 * 36;
        const float* b = Bs + st * 128 * 36;
        #pragma unroll
        for (int ks = 0; ks < BK / 8; ks++) {
            wmma::fragment<wmma::matrix_a, 16, 16, 8, wmma::precision::tf32, wmma::row_major> af[2];
            wmma::fragment<wmma::matrix_b, 16, 16, 8, wmma::precision::tf32, wmma::col_major> bf[4];
            #pragma unroll
            for (int i = 0; i < 2; i++)
                wmma::load_matrix_sync(af[i], a + (wm * 32 + i * 16) * 36 + ks * 8, 36);
            #pragma unroll
            for (int j = 0; j < 4; j++)
                wmma::load_matrix_sync(bf[j], b + (wn * 64 + j * 16) * 36 + ks * 8, 36);
            #pragma unroll
            for (int i = 0; i < 2; i++)
                #pragma unroll
                for (int j = 0; j < 4; j++)
                    wmma::mma_sync(acc[i][j], af[i], bf[j], acc[i][j]);
        }
        if (kt + 2 < HID / BK) issue(kt + 2);
        cp_commit();
    }
    #pragma unroll
    for (int i = 0; i < 2; i++)
        #pragma unroll
        for (int j = 0; j < 4; j++) {
            size_t r = tm + wm * 32 + i * 16;
            size_t n = tn + wn * 64 + j * 16;
            wmma::store_matrix_sync(g_xg + r * NGATE + n, acc[i][j], NGATE, wmma::mem_row_major);
        }
}

// ------------------------------------------------------------------ phase B (persistent, fp16 operands)
#define BSMEM ((32 * WHH_LD + 3 * 64 * HA_LD) * 2 + (64 * 36 + 8 * 65 + 32 + 24) * 4)
__global__ void __launch_bounds__(256) lstm_kernel(const float* __restrict__ Wh,
                                                   const float* __restrict__ h0,
                                                   const float* __restrict__ c0,
                                                   const float* __restrict__ bx,
                                                   const float* __restrict__ bh,
                                                   const float* __restrict__ peep,
                                                   const float* __restrict__ bgate,
                                                   float* __restrict__ out) {
    extern __shared__ __half smh[];
    __half* Whs = smh;                        // [32][1032] fp16
    __half* hAs = smh + 32 * WHH_LD;          // [3][64][136] fp16
    float*  hgS = (float*)(hAs + 3 * 64 * HA_LD);  // [64][36]
    float*  cS  = hgS + 64 * 36;              // [8][65]
    float*  cb  = cS + 8 * 65;                // [32]
    float*  ps  = cb + 32;                    // [24]

    const int tid = threadIdx.x;
    const int wid = tid >> 5;
    const int wb = wid & 3, wn = wid >> 2;
    const int k0 = blockIdx.x * 8;
    const int grp = blockIdx.x >> 4;

    // one-time: stage + convert this CTA's Wh slice (32 rows x 1024 fp32 -> fp16)
    #pragma unroll 4
    for (int i = 0; i < 32; i++) {
        int li = tid + i * 256;               // float4 idx 0..8191
        int n = li >> 8, c4 = li & 255;       // row 0..31, float4 col
        int g = n >> 3, kl = n & 7;
        const float4 v = *(const float4*)(Wh + ((size_t)(g * HID + k0 + kl)) * HID + c4 * 4);
        __half* d = Whs + n * WHH_LD + c4 * 4;
        d[0] = __float2half(v.x);
        d[1] = __float2half(v.y);
        d[2] = __float2half(v.z);
        d[3] = __float2half(v.w);
    }
    if (tid < 32) {
        int g = tid >> 3, kl = tid & 7;
        cb[tid] = bx[g * HID + k0 + kl] + bh[g * HID + k0 + kl] + bgate[g * HID + k0 + kl];
    }
    if (tid < 24) ps[tid] = peep[(tid >> 3) * HID + k0 + (tid & 7)];
    #pragma unroll
    for (int rep = 0; rep < 2; rep++) {
        int p = tid + rep * 256;
        int b = p >> 3, kl = p & 7;
        cS[kl * 65 + b] = c0[(size_t)b * HID + k0 + kl];
        g_h[0][blockIdx.x * 512 + p] = __float2half(h0[(size_t)b * HID + k0 + kl]);  // seed h0 slice
    }
    __syncthreads();
    if (tid == 0)
        asm volatile("red.release.gpu.global.add.s32 [%0], %1;"
                     :: "l"(g_cnt8 + grp), "r"(1) : "memory");

    for (int t = 0; t < SEQ; t++) {
        const int need = 16 * (t + 1);

        // prefetch this step's input-gate preactivations (independent of h_t)
        float xi[2][4];
        #pragma unroll
        for (int rep = 0; rep < 2; rep++) {
            int p = tid + rep * 256;
            int b = p >> 3, kl = p & 7;
            const float* xr = g_xg + (size_t)(b * SEQ + t) * NGATE + k0 + kl;
            xi[rep][0] = __ldg(xr);
            xi[rep][1] = __ldg(xr + HID);
            xi[rep][2] = __ldg(xr + 2 * HID);
            xi[rep][3] = __ldg(xr + 3 * HID);
        }

        const __half* hsrc = g_h[t & 3];
        auto issueH = [&](int kc) {           // chunk kc = 128 k-values, 16KB contiguous
            __half* dst = hAs + (kc % 3) * 64 * HA_LD;
            const __half* src = hsrc + kc * 8192;
            #pragma unroll
            for (int i = 0; i < 4; i++) {
                int li = tid + i * 256;       // 0..1023
                int kb = li >> 6;             // local kblk 0..15
                int b  = li & 63;
                cp16(dst + b * HA_LD + kb * 8, src + kb * 512 + b * 8);
            }
        };

        // wavefront gating: chunk kc waits only on producer group kc
        if (tid == 0) {
            while (ld_acq(&g_cnt8[0]) < need) __nanosleep(32);
            while (ld_acq(&g_cnt8[1]) < need) __nanosleep(32);
        }
        __syncthreads();
        issueH(0); cp_commit();
        issueH(1); cp_commit();

        wmma::fragment<wmma::accumulator, 16, 16, 16, float> acc0, acc1;
        wmma::fill_fragment(acc0, 0.0f);
        wmma::fill_fragment(acc1, 0.0f);

        for (int kc = 0; kc < 8; kc++) {
            cp_wait<1>();
            if (tid == 0 && kc < 6) {
                while (ld_acq(&g_cnt8[kc + 2]) < need) __nanosleep(32);
            }
            __syncthreads();
            const __half* a = hAs + (kc % 3) * 64 * HA_LD;
            #pragma unroll
            for (int ks = 0; ks < 8; ks++) {
                wmma::fragment<wmma::matrix_a, 16, 16, 16, __half, wmma::row_major> af;
                wmma::fragment<wmma::matrix_b, 16, 16, 16, __half, wmma::col_major> bf;
                wmma::load_matrix_sync(af, a + (wb * 16) * HA_LD + ks * 16, HA_LD);
                wmma::load_matrix_sync(bf, Whs + (wn * 16) * WHH_LD + kc * 128 + ks * 16, WHH_LD);
                if (ks & 1) wmma::mma_sync(acc1, af, bf, acc1);
                else        wmma::mma_sync(acc0, af, bf, acc0);
            }
            if (kc < 6) issueH(kc + 2);
            cp_commit();
        }
        #pragma unroll
        for (int e = 0; e < acc0.num_elements; e++) acc0.x[e] += acc1.x[e];
        wmma::store_matrix_sync(hgS + (wb * 16) * 36 + wn * 16, acc0, 36, wmma::mem_row_major);
        __syncthreads();

        // epilogue: gates; h written coalesced (1KB contiguous fp16)
        __half* hdst = g_h[(t + 1) & 3] + blockIdx.x * 512;
        float hn[2];
        #pragma unroll
        for (int rep = 0; rep < 2; rep++) {
            int p = tid + rep * 256;
            int b = p >> 3, kl = p & 7;
            float c = cS[kl * 65 + b];
            float pi = xi[rep][0] + hgS[b * 36 +      kl] + ps[kl]     * c + cb[kl];
            float pf = xi[rep][1] + hgS[b * 36 +  8 + kl] + ps[8 + kl] * c + cb[8 + kl];
            float pc = xi[rep][2] + hgS[b * 36 + 16 + kl]                  + cb[16 + kl];
            float po = xi[rep][3] + hgS[b * 36 + 24 + kl]                  + cb[24 + kl];
            float cn = sigm(pf) * c + sigm(pi) + tanhf(pc);
            hn[rep] = sigm(po + ps[16 + kl] * cn) * tanhf(cn);
            cS[kl * 65 + b] = cn;
            hdst[p] = __float2half(hn[rep]);
        }
        __syncthreads();                    // all h stores happen-before the release
        if (tid == 0)
            asm volatile("red.release.gpu.global.add.s32 [%0], %1;"
                         :: "l"(g_cnt8 + grp), "r"(1) : "memory");

        // out stores AFTER release — off the critical handshake path
        #pragma unroll
        for (int rep = 0; rep < 2; rep++) {
            int p = tid + rep * 256;
            int b = p >> 3, kl = p & 7;
            out[(size_t)(b * SEQ + t) * HID + k0 + kl] = hn[rep];
        }
    }
}

extern "C" void kernel_launch(void* const* d_in, const int* in_sizes, int n_in,
                              void* d_out, int out_size) {
    const float* x     = (const float*)d_in[0];
    const float* h0    = (const float*)d_in[1];
    const float* c0    = (const float*)d_in[2];
    const float* Wx    = (const float*)d_in[3];
    const float* bx    = (const float*)d_in[4];
    const float* Wh    = (const float*)d_in[5];
    const float* bh    = (const float*)d_in[6];
    const float* peep  = (const float*)d_in[7];
    const float* bgate = (const float*)d_in[8];
    float* out = (float*)d_out;

    cudaFuncSetAttribute(gemm_xg_kernel, cudaFuncAttributeMaxDynamicSharedMemorySize, ASMEM);
    cudaFuncSetAttribute(lstm_kernel, cudaFuncAttributeMaxDynamicSharedMemorySize, BSMEM);

    gemm_xg_kernel<<<dim3(32, 128), 256, ASMEM>>>(x, Wx);
    lstm_kernel<<<NCTA, 256, BSMEM>>>(Wh, h0, c0, bx, bh, peep, bgate, out);
}

// round 8
// speedup vs baseline: 1.3954x; 1.3954x over previous
#include <cuda_runtime.h>
#include <cuda_fp16.h>
#include <mma.h>
#include <cstdint>

using namespace nvcuda;

#define HID   1024
#define BATCH 64
#define SEQ   256
#define NGATE 4096
#define NCTA  128
#define WHH_LD 1032
#define HA_LD 136
#define CH (64 * HA_LD)

__device__ float  g_xg[(size_t)BATCH * SEQ * NGATE];  // [b*SEQ+t][g*HID+k] fp32
__device__ __half g_xh[(size_t)BATCH * SEQ * HID];    // fp16 x
__device__ __half g_wxh[(size_t)NGATE * HID];         // fp16 Wx
__device__ __half g_whh[(size_t)NGATE * HID];         // fp16 Wh
// blocked h ring (fp16): g_h[slot][kblk*512 + b*8 + kl]
__device__ __half g_h[4][BATCH * HID];
__device__ int    g_cnt8[8];                          // group counters (16 CTAs each)

__device__ __forceinline__ void cp16(void* s, const void* g) {
    uint32_t sa = (uint32_t)__cvta_generic_to_shared(s);
    asm volatile("cp.async.cg.shared.global [%0], [%1], 16;\n" :: "r"(sa), "l"(g));
}
__device__ __forceinline__ void cp_commit() { asm volatile("cp.async.commit_group;\n"); }
template<int N> __device__ __forceinline__ void cp_wait() {
    asm volatile("cp.async.wait_group %0;\n" :: "n"(N));
}
__device__ __forceinline__ float sigm(float x) { return 1.0f / (1.0f + __expf(-x)); }
__device__ __forceinline__ int ld_relaxed(const int* p) {
    int v;
    asm volatile("ld.relaxed.gpu.global.s32 %0, [%1];" : "=r"(v) : "l"(p) : "memory");
    return v;
}

// ------------------------------------------------------------------ convert to fp16
__global__ void convert_kernel(const float* __restrict__ x,
                               const float* __restrict__ Wx,
                               const float* __restrict__ Wh,
                               const float* __restrict__ h0) {
    size_t idx = (size_t)blockIdx.x * blockDim.x + threadIdx.x;
    size_t tot = (size_t)gridDim.x * blockDim.x;
    for (size_t i = idx; i < (size_t)BATCH * SEQ * HID; i += tot) g_xh[i]  = __float2half(x[i]);
    for (size_t i = idx; i < (size_t)NGATE * HID; i += tot)       g_wxh[i] = __float2half(Wx[i]);
    for (size_t i = idx; i < (size_t)NGATE * HID; i += tot)       g_whh[i] = __float2half(Wh[i]);
    for (size_t i = idx; i < (size_t)BATCH * HID; i += tot) {
        int b = (int)(i >> 10), k = (int)(i & 1023);
        g_h[0][(k >> 3) * 512 + b * 8 + (k & 7)] = __float2half(h0[i]);
    }
}

// ------------------------------------------------------------------ phase A (fp16 wmma)
#define BK 32
#define A_LD 40
#define ASMEM (2 * 3 * 128 * A_LD * 2)
__global__ void __launch_bounds__(256, 2) gemm_xg_kernel() {
    extern __shared__ __half smh[];
    __half* As = smh;                     // [3][128][40]
    __half* Bs = smh + 3 * 128 * A_LD;    // [3][128][40]
    const int tid = threadIdx.x;
    const int wid = tid >> 5;
    const int wm = wid & 3, wn = wid >> 2;
    const int tm = blockIdx.y * 128;
    const int tn = blockIdx.x * 128;

    if (blockIdx.x == 0 && blockIdx.y == 0 && tid < 8) g_cnt8[tid] = 16;  // h(0) published

    wmma::fragment<wmma::accumulator, 16, 16, 16, float> acc[2][4];
    #pragma unroll
    for (int i = 0; i < 2; i++)
        #pragma unroll
        for (int j = 0; j < 4; j++) wmma::fill_fragment(acc[i][j], 0.0f);

    auto issue = [&](int kt) {
        int st = kt % 3;
        int kk = kt * BK;
        __half* a = As + st * 128 * A_LD;
        __half* b = Bs + st * 128 * A_LD;
        #pragma unroll
        for (int i = 0; i < 4; i++) {
            int li = tid + i * 256;          // 0..1023
            int half_sel = li >> 9;
            int lj = li & 511;
            int r = lj >> 2, sg = lj & 3;
            if (half_sel == 0)
                cp16(a + r * A_LD + sg * 8, g_xh  + (size_t)(tm + r) * HID + kk + sg * 8);
            else
                cp16(b + r * A_LD + sg * 8, g_wxh + (size_t)(tn + r) * HID + kk + sg * 8);
        }
    };
    issue(0); cp_commit();
    issue(1); cp_commit();

    for (int kt = 0; kt < HID / BK; kt++) {
        cp_wait<1>();
        __syncthreads();
        const int st = kt % 3;
        const __half* a = As + st * 128 * A_LD;
        const __half* b = Bs + st * 128 * A_LD;
        #pragma unroll
        for (int ks = 0; ks < 2; ks++) {
            wmma::fragment<wmma::matrix_a, 16, 16, 16, __half, wmma::row_major> af[2];
            wmma::fragment<wmma::matrix_b, 16, 16, 16, __half, wmma::col_major> bf[4];
            #pragma unroll
            for (int i = 0; i < 2; i++)
                wmma::load_matrix_sync(af[i], a + (wm * 32 + i * 16) * A_LD + ks * 16, A_LD);
            #pragma unroll
            for (int j = 0; j < 4; j++)
                wmma::load_matrix_sync(bf[j], b + (wn * 64 + j * 16) * A_LD + ks * 16, A_LD);
            #pragma unroll
            for (int i = 0; i < 2; i++)
                #pragma unroll
                for (int j = 0; j < 4; j++)
                    wmma::mma_sync(acc[i][j], af[i], bf[j], acc[i][j]);
        }
        if (kt + 2 < HID / BK) issue(kt + 2);
        cp_commit();
    }
    #pragma unroll
    for (int i = 0; i < 2; i++)
        #pragma unroll
        for (int j = 0; j < 4; j++) {
            size_t r = tm + wm * 32 + i * 16;
            size_t n = tn + wn * 64 + j * 16;
            wmma::store_matrix_sync(g_xg + r * NGATE + n, acc[i][j], NGATE, wmma::mem_row_major);
        }
}

// ------------------------------------------------------------------ phase B (persistent, 512 thr, K-split-2)
#define BSMEM ((32 * WHH_LD + 6 * CH) * 2 + (2 * 64 * 36 + 8 * 65 + 32 + 24) * 4)
__global__ void __launch_bounds__(512, 1) lstm_kernel(const float* __restrict__ c0,
                                                      const float* __restrict__ bx,
                                                      const float* __restrict__ bh,
                                                      const float* __restrict__ peep,
                                                      const float* __restrict__ bgate,
                                                      float* __restrict__ out) {
    extern __shared__ __half smh[];
    __half* Whs = smh;                        // [32][1032] fp16
    __half* hAs = smh + 32 * WHH_LD;          // [6][64][136] fp16 (3 bufs x 2 K-halves)
    float*  hgS = (float*)(hAs + 6 * CH);     // [2][64][36] fp32 partials
    float*  cS  = hgS + 2 * 64 * 36;          // [8][65]
    float*  cb  = cS + 8 * 65;                // [32]
    float*  ps  = cb + 32;                    // [24]

    const int tid = threadIdx.x;
    const int wid = tid >> 5;
    const int kh  = wid >> 3;                 // K-half 0/1
    const int w8  = wid & 7;
    const int wb  = w8 & 3, wn = w8 >> 2;     // M tile 0..3, N tile 0..1
    const int k0  = blockIdx.x * 8;
    const int grp = blockIdx.x >> 4;

    // one-time: stage this CTA's fp16 Wh slice (32 rows x 1024)
    #pragma unroll
    for (int i = 0; i < 8; i++) {
        int li = tid + i * 512;               // 0..4095
        int n = li >> 7, sg = li & 127;       // row 0..31, 16B seg
        int g = n >> 3, kl = n & 7;
        cp16(Whs + n * WHH_LD + sg * 8,
             g_whh + ((size_t)(g * HID + k0 + kl)) * HID + sg * 8);
    }
    cp_commit();
    if (tid < 32) {
        int g = tid >> 3, kl = tid & 7;
        cb[tid] = bx[g * HID + k0 + kl] + bh[g * HID + k0 + kl] + bgate[g * HID + k0 + kl];
    }
    if (tid < 24) ps[tid] = peep[(tid >> 3) * HID + k0 + (tid & 7)];
    {
        int b = tid >> 3, kl = tid & 7;
        cS[kl * 65 + b] = c0[(size_t)b * HID + k0 + kl];
    }
    cp_wait<0>();
    __syncthreads();

    for (int t = 0; t < SEQ; t++) {
        // prefetch this step's input-gate preactivations (independent of h_t)
        int b = tid >> 3, kl = tid & 7;
        const float* xr = g_xg + (size_t)(b * SEQ + t) * NGATE + k0 + kl;
        float xi0 = __ldg(xr);
        float xi1 = __ldg(xr + HID);
        float xi2 = __ldg(xr + 2 * HID);
        float xi3 = __ldg(xr + 3 * HID);

        // tid0 polls the 8 group counters with backoff, then acquires
        if (tid == 0) {
            const int need = 16 * (t + 1);
            while (true) {
                int m = ld_relaxed(g_cnt8);
                #pragma unroll
                for (int j = 1; j < 8; j++) { int v = ld_relaxed(g_cnt8 + j); m = v < m ? v : m; }
                if (m >= need) break;
                __nanosleep(64);
            }
            asm volatile("fence.acq_rel.gpu;" ::: "memory");
        }
        __syncthreads();

        const __half* hsrc = g_h[t & 3];
        // group j: chunk j (K-half 0) + chunk 4+j (K-half 1), 32KB
        auto issueG = [&](int j) {
            __half* d0 = hAs + (j % 3) * CH;
            __half* d1 = hAs + (3 + j % 3) * CH;
            const __half* s0 = hsrc + j * 8192;
            const __half* s1 = hsrc + (4 + j) * 8192;
            #pragma unroll
            for (int i = 0; i < 2; i++) {
                int li = tid + i * 512;       // 0..1023
                int kb = li >> 6, bb = li & 63;
                cp16(d0 + bb * HA_LD + kb * 8, s0 + kb * 512 + bb * 8);
                cp16(d1 + bb * HA_LD + kb * 8, s1 + kb * 512 + bb * 8);
            }
        };
        issueG(0); cp_commit();
        issueG(1); cp_commit();

        wmma::fragment<wmma::accumulator, 16, 16, 16, float> acc0, acc1;
        wmma::fill_fragment(acc0, 0.0f);
        wmma::fill_fragment(acc1, 0.0f);

        for (int it = 0; it < 4; it++) {
            cp_wait<1>();
            __syncthreads();
            const __half* a = hAs + (kh * 3 + it % 3) * CH;
            const int kcol = (kh * 4 + it) * 128;
            #pragma unroll
            for (int ks = 0; ks < 8; ks++) {
                wmma::fragment<wmma::matrix_a, 16, 16, 16, __half, wmma::row_major> af;
                wmma::fragment<wmma::matrix_b, 16, 16, 16, __half, wmma::col_major> bf;
                wmma::load_matrix_sync(af, a + (wb * 16) * HA_LD + ks * 16, HA_LD);
                wmma::load_matrix_sync(bf, Whs + (wn * 16) * WHH_LD + kcol + ks * 16, WHH_LD);
                if (ks & 1) wmma::mma_sync(acc1, af, bf, acc1);
                else        wmma::mma_sync(acc0, af, bf, acc0);
            }
            if (it < 2) issueG(it + 2);
            cp_commit();
        }
        #pragma unroll
        for (int e = 0; e < acc0.num_elements; e++) acc0.x[e] += acc1.x[e];
        wmma::store_matrix_sync(hgS + kh * (64 * 36) + (wb * 16) * 36 + wn * 16,
                                acc0, 36, wmma::mem_row_major);
        __syncthreads();

        // epilogue: sum K-half partials, gates; h written coalesced (1KB contiguous fp16)
        __half* hdst = g_h[(t + 1) & 3] + blockIdx.x * 512;
        float c  = cS[kl * 65 + b];
        float h0v = hgS[b * 36 +      kl] + hgS[64 * 36 + b * 36 +      kl];
        float h1v = hgS[b * 36 +  8 + kl] + hgS[64 * 36 + b * 36 +  8 + kl];
        float h2v = hgS[b * 36 + 16 + kl] + hgS[64 * 36 + b * 36 + 16 + kl];
        float h3v = hgS[b * 36 + 24 + kl] + hgS[64 * 36 + b * 36 + 24 + kl];
        float pi = xi0 + h0v + ps[kl]     * c + cb[kl];
        float pf = xi1 + h1v + ps[8 + kl] * c + cb[8 + kl];
        float pc = xi2 + h2v                  + cb[16 + kl];
        float po = xi3 + h3v                  + cb[24 + kl];
        float cn = sigm(pf) * c + sigm(pi) + tanhf(pc);
        float hn = sigm(po + ps[16 + kl] * cn) * tanhf(cn);
        cS[kl * 65 + b] = cn;
        hdst[tid] = __float2half(hn);
        __syncthreads();                    // all h stores happen-before the release
        if (tid == 0)
            asm volatile("red.release.gpu.global.add.s32 [%0], %1;"
                         :: "l"(g_cnt8 + grp), "r"(1) : "memory");

        // out store AFTER release — off the critical handshake path
        out[(size_t)(b * SEQ + t) * HID + k0 + kl] = hn;
    }
}

extern "C" void kernel_launch(void* const* d_in, const int* in_sizes, int n_in,
                              void* d_out, int out_size) {
    const float* x     = (const float*)d_in[0];
    const float* h0    = (const float*)d_in[1];
    const float* c0    = (const float*)d_in[2];
    const float* Wx    = (const float*)d_in[3];
    const float* bx    = (const float*)d_in[4];
    const float* Wh    = (const float*)d_in[5];
    const float* bh    = (const float*)d_in[6];
    const float* peep  = (const float*)d_in[7];
    const float* bgate = (const float*)d_in[8];
    float* out = (float*)d_out;

    cudaFuncSetAttribute(gemm_xg_kernel, cudaFuncAttributeMaxDynamicSharedMemorySize, ASMEM);
    cudaFuncSetAttribute(lstm_kernel, cudaFuncAttributeMaxDynamicSharedMemorySize, BSMEM);

    convert_kernel<<<1024, 256>>>(x, Wx, Wh, h0);
    gemm_xg_kernel<<<dim3(32, 128), 256, ASMEM>>>();
    lstm_kernel<<<NCTA, 512, BSMEM>>>(c0, bx, bh, peep, bgate, out);
}

// round 9
// speedup vs baseline: 2.5394x; 1.8198x over previous
#include <cuda_runtime.h>
#include <cuda_fp16.h>
#include <mma.h>
#include <cstdint>

using namespace nvcuda;

#define HID   1024
#define BATCH 64
#define SEQ   256
#define NGATE 4096
#define NCTA  128
#define WHH_LD 1032
#define HA_LD 136
#define MB 32            // batches per CTA (2 batch groups)
#define CHB (32 * HA_LD) // one h chunk buffer (32 b x 128 k, padded)

__device__ float  g_xg[(size_t)BATCH * SEQ * NGATE];  // [b*SEQ+t][g*HID+k] fp32
__device__ __half g_xh[(size_t)BATCH * SEQ * HID];    // fp16 x
__device__ __half g_wxh[(size_t)NGATE * HID];         // fp16 Wx
__device__ __half g_whh[(size_t)NGATE * HID];         // fp16 Wh
__device__ __half g_h[4][BATCH * HID];                // h ring, natural [b][k] layout
__device__ int    g_cnt16[16];                        // [bg*8+grp]: 8 CTAs each

__device__ __forceinline__ void cp16(void* s, const void* g) {
    uint32_t sa = (uint32_t)__cvta_generic_to_shared(s);
    asm volatile("cp.async.cg.shared.global [%0], [%1], 16;\n" :: "r"(sa), "l"(g));
}
__device__ __forceinline__ void cp_commit() { asm volatile("cp.async.commit_group;\n"); }
template<int N> __device__ __forceinline__ void cp_wait() {
    asm volatile("cp.async.wait_group %0;\n" :: "n"(N));
}
__device__ __forceinline__ float sigm(float x) { return 1.0f / (1.0f + __expf(-x)); }
__device__ __forceinline__ int ld_relaxed(const int* p) {
    int v;
    asm volatile("ld.relaxed.gpu.global.s32 %0, [%1];" : "=r"(v) : "l"(p) : "memory");
    return v;
}

// ------------------------------------------------------------------ convert to fp16
__global__ void convert_kernel(const float* __restrict__ x,
                               const float* __restrict__ Wx,
                               const float* __restrict__ Wh,
                               const float* __restrict__ h0) {
    size_t idx = (size_t)blockIdx.x * blockDim.x + threadIdx.x;
    size_t tot = (size_t)gridDim.x * blockDim.x;
    for (size_t i = idx; i < (size_t)BATCH * SEQ * HID; i += tot) g_xh[i]  = __float2half(x[i]);
    for (size_t i = idx; i < (size_t)NGATE * HID; i += tot)       g_wxh[i] = __float2half(Wx[i]);
    for (size_t i = idx; i < (size_t)NGATE * HID; i += tot)       g_whh[i] = __float2half(Wh[i]);
    for (size_t i = idx; i < (size_t)BATCH * HID; i += tot)       g_h[0][i] = __float2half(h0[i]);
}

// ------------------------------------------------------------------ phase A (fp16 wmma)
#define BK 32
#define A_LD 40
#define ASMEM (2 * 3 * 128 * A_LD * 2)
__global__ void __launch_bounds__(256, 2) gemm_xg_kernel() {
    extern __shared__ __half smh[];
    __half* As = smh;                     // [3][128][40]
    __half* Bs = smh + 3 * 128 * A_LD;    // [3][128][40]
    const int tid = threadIdx.x;
    const int wid = tid >> 5;
    const int wm = wid & 3, wn = wid >> 2;
    const int tm = blockIdx.y * 128;
    const int tn = blockIdx.x * 128;

    if (blockIdx.x == 0 && blockIdx.y == 0 && tid < 16) g_cnt16[tid] = 8;  // h(0) published

    wmma::fragment<wmma::accumulator, 16, 16, 16, float> acc[2][4];
    #pragma unroll
    for (int i = 0; i < 2; i++)
        #pragma unroll
        for (int j = 0; j < 4; j++) wmma::fill_fragment(acc[i][j], 0.0f);

    auto issue = [&](int kt) {
        int st = kt % 3;
        int kk = kt * BK;
        __half* a = As + st * 128 * A_LD;
        __half* b = Bs + st * 128 * A_LD;
        #pragma unroll
        for (int i = 0; i < 4; i++) {
            int li = tid + i * 256;          // 0..1023
            int half_sel = li >> 9;
            int lj = li & 511;
            int r = lj >> 2, sg = lj & 3;
            if (half_sel == 0)
                cp16(a + r * A_LD + sg * 8, g_xh  + (size_t)(tm + r) * HID + kk + sg * 8);
            else
                cp16(b + r * A_LD + sg * 8, g_wxh + (size_t)(tn + r) * HID + kk + sg * 8);
        }
    };
    issue(0); cp_commit();
    issue(1); cp_commit();

    for (int kt = 0; kt < HID / BK; kt++) {
        cp_wait<1>();
        __syncthreads();
        const int st = kt % 3;
        const __half* a = As + st * 128 * A_LD;
        const __half* b = Bs + st * 128 * A_LD;
        #pragma unroll
        for (int ks = 0; ks < 2; ks++) {
            wmma::fragment<wmma::matrix_a, 16, 16, 16, __half, wmma::row_major> af[2];
            wmma::fragment<wmma::matrix_b, 16, 16, 16, __half, wmma::col_major> bf[4];
            #pragma unroll
            for (int i = 0; i < 2; i++)
                wmma::load_matrix_sync(af[i], a + (wm * 32 + i * 16) * A_LD + ks * 16, A_LD);
            #pragma unroll
            for (int j = 0; j < 4; j++)
                wmma::load_matrix_sync(bf[j], b + (wn * 64 + j * 16) * A_LD + ks * 16, A_LD);
            #pragma unroll
            for (int i = 0; i < 2; i++)
                #pragma unroll
                for (int j = 0; j < 4; j++)
                    wmma::mma_sync(acc[i][j], af[i], bf[j], acc[i][j]);
        }
        if (kt + 2 < HID / BK) issue(kt + 2);
        cp_commit();
    }
    #pragma unroll
    for (int i = 0; i < 2; i++)
        #pragma unroll
        for (int j = 0; j < 4; j++) {
            size_t r = tm + wm * 32 + i * 16;
            size_t n = tn + wn * 64 + j * 16;
            wmma::store_matrix_sync(g_xg + r * NGATE + n, acc[i][j], NGATE, wmma::mem_row_major);
        }
}

// ------------------------------------------------------------------ phase B
// 2 batch groups x 64 channel blocks. CTA owns 32 batches x 16 channels (64 gate rows).
#define BSMEM ((64 * WHH_LD + 6 * CHB) * 2 + (2 * 32 * 68 + 16 * 33 + 64 + 48) * 4)
__global__ void __launch_bounds__(512, 1) lstm_kernel(const float* __restrict__ c0,
                                                      const float* __restrict__ bx,
                                                      const float* __restrict__ bh,
                                                      const float* __restrict__ peep,
                                                      const float* __restrict__ bgate,
                                                      float* __restrict__ out) {
    extern __shared__ __half smh[];
    __half* Whs = smh;                        // [64][1032] fp16
    __half* hAs = smh + 64 * WHH_LD;          // [6][32][136] fp16 (3 bufs x 2 K-halves)
    float*  hgS = (float*)(hAs + 6 * CHB);    // [2][32][68] fp32 partials
    float*  cS  = hgS + 2 * 32 * 68;          // [16][33]
    float*  cb  = cS + 16 * 33;               // [64]
    float*  ps  = cb + 64;                    // [48]

    const int tid = threadIdx.x;
    const int wid = tid >> 5;
    const int kh  = wid >> 3;                 // K-half 0/1
    const int w8  = wid & 7;
    const int mt  = w8 & 1, nt = w8 >> 1;     // M tile 0..1, N tile 0..3
    const int j   = blockIdx.x & 63;          // channel block
    const int bg  = blockIdx.x >> 6;          // batch group
    const int c0ch = j * 16;                  // first channel
    const int grp = bg * 8 + (j >> 3);

    // one-time: stage this CTA's fp16 Wh slice (64 rows x 1024)
    #pragma unroll
    for (int i = 0; i < 16; i++) {
        int li = tid + i * 512;               // 0..8191
        int n = li >> 7, sg = li & 127;       // row 0..63, 16B seg
        int g = n >> 4, ch = n & 15;
        cp16(Whs + n * WHH_LD + sg * 8,
             g_whh + ((size_t)(g * HID + c0ch + ch)) * HID + sg * 8);
    }
    cp_commit();
    if (tid < 64) {
        int g = tid >> 4, ch = tid & 15;
        cb[tid] = bx[g * HID + c0ch + ch] + bh[g * HID + c0ch + ch] + bgate[g * HID + c0ch + ch];
    }
    if (tid < 48) ps[tid] = peep[(tid >> 4) * HID + c0ch + (tid & 15)];
    {
        int b = tid >> 4, ch = tid & 15;      // local batch, channel
        cS[ch * 33 + b] = c0[(size_t)(bg * MB + b) * HID + c0ch + ch];
    }
    cp_wait<0>();
    __syncthreads();

    const int b  = tid >> 4;                  // local batch 0..31
    const int ch = tid & 15;                  // channel 0..15
    const size_t gb = (size_t)(bg * MB + b);  // global batch

    for (int t = 0; t < SEQ; t++) {
        // prefetch this step's input-gate preactivations (independent of h_t)
        const float* xr = g_xg + (gb * SEQ + t) * NGATE + c0ch + ch;
        float xi0 = __ldg(xr);
        float xi1 = __ldg(xr + HID);
        float xi2 = __ldg(xr + 2 * HID);
        float xi3 = __ldg(xr + 3 * HID);

        // tid0 polls this batch group's 8 counters with backoff, then acquires
        if (tid == 0) {
            const int need = 8 * (t + 1);
            const int* cnt = g_cnt16 + bg * 8;
            while (true) {
                int m = ld_relaxed(cnt);
                #pragma unroll
                for (int q = 1; q < 8; q++) { int v = ld_relaxed(cnt + q); m = v < m ? v : m; }
                if (m >= need) break;
                __nanosleep(64);
            }
            asm volatile("fence.acq_rel.gpu;" ::: "memory");
        }
        __syncthreads();

        const __half* hsrc = g_h[t & 3] + (size_t)bg * MB * HID;
        // group q: chunk q (K-half 0, k in [128q,128q+128)) + chunk 4+q (K-half 1)
        auto issueG = [&](int q) {
            __half* d0 = hAs + (q % 3) * CHB;
            __half* d1 = hAs + (3 + q % 3) * CHB;
            const __half* s0 = hsrc + q * 128;
            const __half* s1 = hsrc + (4 + q) * 128;
            #pragma unroll
            for (int i = 0; i < 2; i++) {
                int li = tid + i * 512;       // 0..1023
                int hs = li >> 9;             // which half
                int lj = li & 511;
                int bb = lj >> 4, sg = lj & 15;   // batch row, 16B seg
                if (hs == 0)
                    cp16(d0 + bb * HA_LD + sg * 8, s0 + (size_t)bb * HID + sg * 8);
                else
                    cp16(d1 + bb * HA_LD + sg * 8, s1 + (size_t)bb * HID + sg * 8);
            }
        };
        issueG(0); cp_commit();
        issueG(1); cp_commit();

        wmma::fragment<wmma::accumulator, 16, 16, 16, float> acc0, acc1;
        wmma::fill_fragment(acc0, 0.0f);
        wmma::fill_fragment(acc1, 0.0f);

        for (int it = 0; it < 4; it++) {
            cp_wait<1>();
            __syncthreads();
            const __half* a = hAs + (kh * 3 + it % 3) * CHB;
            const int kcol = (kh * 4 + it) * 128;
            #pragma unroll
            for (int ks = 0; ks < 8; ks++) {
                wmma::fragment<wmma::matrix_a, 16, 16, 16, __half, wmma::row_major> af;
                wmma::fragment<wmma::matrix_b, 16, 16, 16, __half, wmma::col_major> bf;
                wmma::load_matrix_sync(af, a + (mt * 16) * HA_LD + ks * 16, HA_LD);
                wmma::load_matrix_sync(bf, Whs + (nt * 16) * WHH_LD + kcol + ks * 16, WHH_LD);
                if (ks & 1) wmma::mma_sync(acc1, af, bf, acc1);
                else        wmma::mma_sync(acc0, af, bf, acc0);
            }
            if (it < 2) issueG(it + 2);
            cp_commit();
        }
        #pragma unroll
        for (int e = 0; e < acc0.num_elements; e++) acc0.x[e] += acc1.x[e];
        wmma::store_matrix_sync(hgS + kh * (32 * 68) + (mt * 16) * 68 + nt * 16,
                                acc0, 68, wmma::mem_row_major);
        __syncthreads();

        // epilogue: sum K-half partials, gates; h written to natural [b][k] layout
        float c  = cS[ch * 33 + b];
        float h0v = hgS[b * 68 +      ch] + hgS[32 * 68 + b * 68 +      ch];
        float h1v = hgS[b * 68 + 16 + ch] + hgS[32 * 68 + b * 68 + 16 + ch];
        float h2v = hgS[b * 68 + 32 + ch] + hgS[32 * 68 + b * 68 + 32 + ch];
        float h3v = hgS[b * 68 + 48 + ch] + hgS[32 * 68 + b * 68 + 48 + ch];
        float pi = xi0 + h0v + ps[ch]      * c + cb[ch];
        float pf = xi1 + h1v + ps[16 + ch] * c + cb[16 + ch];
        float pc = xi2 + h2v                   + cb[32 + ch];
        float po = xi3 + h3v                   + cb[48 + ch];
        float cn = sigm(pf) * c + sigm(pi) + tanhf(pc);
        float hn = sigm(po + ps[32 + ch] * cn) * tanhf(cn);
        cS[ch * 33 + b] = cn;
        g_h[(t + 1) & 3][gb * HID + c0ch + ch] = __float2half(hn);
        __syncthreads();                    // all h stores happen-before the release
        if (tid == 0)
            asm volatile("red.release.gpu.global.add.s32 [%0], %1;"
                         :: "l"(g_cnt16 + grp), "r"(1) : "memory");

        // out store AFTER release — off the critical handshake path
        out[(gb * SEQ + t) * HID + c0ch + ch] = hn;
    }
}

extern "C" void kernel_launch(void* const* d_in, const int* in_sizes, int n_in,
                              void* d_out, int out_size) {
    const float* x     = (const float*)d_in[0];
    const float* h0    = (const float*)d_in[1];
    const float* c0    = (const float*)d_in[2];
    const float* Wx    = (const float*)d_in[3];
    const float* bx    = (const float*)d_in[4];
    const float* Wh    = (const float*)d_in[5];
    const float* bh    = (const float*)d_in[6];
    const float* peep  = (const float*)d_in[7];
    const float* bgate = (const float*)d_in[8];
    float* out = (float*)d_out;

    cudaFuncSetAttribute(gemm_xg_kernel, cudaFuncAttributeMaxDynamicSharedMemorySize, ASMEM);
    cudaFuncSetAttribute(lstm_kernel, cudaFuncAttributeMaxDynamicSharedMemorySize, BSMEM);

    convert_kernel<<<1024, 256>>>(x, Wx, Wh, h0);
    gemm_xg_kernel<<<dim3(32, 128), 256, ASMEM>>>();
    lstm_kernel<<<NCTA, 512, BSMEM>>>(c0, bx, bh, peep, bgate, out);
}

// round 10
// speedup vs baseline: 2.5808x; 1.0163x over previous
#include <cuda_runtime.h>
#include <cuda_fp16.h>
#include <mma.h>
#include <cstdint>

using namespace nvcuda;

#define HID   1024
#define BATCH 64
#define SEQ   256
#define NGATE 4096
#define NCTA  128
#define WHH_LD 1032
#define HA_LD 136
#define MB 32
#define CHB (32 * HA_LD)          // one chunk: 32 b x 136 halfs = 8704 B
#define CHB_BYTES (CHB * 2)

__device__ float  g_xg[(size_t)BATCH * SEQ * NGATE];  // [b*SEQ+t][g*HID+k] fp32
__device__ __half g_xh[(size_t)BATCH * SEQ * HID];    // fp16 x
__device__ __half g_wxh[(size_t)NGATE * HID];         // fp16 Wx
__device__ __half g_whh[(size_t)NGATE * HID];         // fp16 Wh
// padded h ring: [slot][bg][kc][b][136]  (pre-padded SMEM image, bulk-copyable)
__device__ __half g_h2[4][2 * 8 * CHB];
__device__ int    g_cnt16[16];                        // [bg*8+grp]: 8 CTAs each

__device__ __forceinline__ void cp16(void* s, const void* g) {
    uint32_t sa = (uint32_t)__cvta_generic_to_shared(s);
    asm volatile("cp.async.cg.shared.global [%0], [%1], 16;\n" :: "r"(sa), "l"(g));
}
__device__ __forceinline__ void cp_commit() { asm volatile("cp.async.commit_group;\n"); }
template<int N> __device__ __forceinline__ void cp_wait() {
    asm volatile("cp.async.wait_group %0;\n" :: "n"(N));
}
__device__ __forceinline__ float sigm(float x) { return 1.0f / (1.0f + __expf(-x)); }
__device__ __forceinline__ int ld_relaxed(const int* p) {
    int v;
    asm volatile("ld.relaxed.gpu.global.s32 %0, [%1];" : "=r"(v) : "l"(p) : "memory");
    return v;
}
__device__ __forceinline__ void mbar_init(uint32_t mbar, uint32_t cnt) {
    asm volatile("mbarrier.init.shared.b64 [%0], %1;" :: "r"(mbar), "r"(cnt) : "memory");
}
__device__ __forceinline__ void mbar_expect_tx(uint32_t mbar, uint32_t tx) {
    asm volatile("mbarrier.arrive.expect_tx.shared.b64 _, [%0], %1;" :: "r"(mbar), "r"(tx) : "memory");
}
__device__ __forceinline__ void mbar_wait(uint32_t mbar, uint32_t parity) {
    asm volatile(
        "{\n\t.reg .pred P;\n"
        "WAIT_%=:\n\t"
        "mbarrier.try_wait.parity.acquire.cta.shared::cta.b64 P, [%0], %1, 0x989680;\n\t"
        "@P bra WAIT_DONE_%=;\n\t"
        "bra WAIT_%=;\n"
        "WAIT_DONE_%=:\n\t}"
        :: "r"(mbar), "r"(parity) : "memory");
}
__device__ __forceinline__ void bulk_ld(uint32_t dst, const void* src, uint32_t bytes, uint32_t mbar) {
    asm volatile(
        "cp.async.bulk.shared::cluster.global.mbarrier::complete_tx::bytes [%0], [%1], %2, [%3];"
        :: "r"(dst), "l"(src), "r"(bytes), "r"(mbar) : "memory");
}

// ------------------------------------------------------------------ convert to fp16
__global__ void convert_kernel(const float* __restrict__ x,
                               const float* __restrict__ Wx,
                               const float* __restrict__ Wh,
                               const float* __restrict__ h0) {
    size_t idx = (size_t)blockIdx.x * blockDim.x + threadIdx.x;
    size_t tot = (size_t)gridDim.x * blockDim.x;
    for (size_t i = idx; i < (size_t)BATCH * SEQ * HID; i += tot) g_xh[i]  = __float2half(x[i]);
    for (size_t i = idx; i < (size_t)NGATE * HID; i += tot)       g_wxh[i] = __float2half(Wx[i]);
    for (size_t i = idx; i < (size_t)NGATE * HID; i += tot)       g_whh[i] = __float2half(Wh[i]);
    for (size_t i = idx; i < (size_t)BATCH * HID; i += tot) {
        int b = (int)(i >> 10), k = (int)(i & 1023);
        g_h2[0][((b >> 5) * 8 + (k >> 7)) * CHB + (b & 31) * HA_LD + (k & 127)] = __float2half(h0[i]);
    }
}

// ------------------------------------------------------------------ phase A (fp16 wmma)
#define BK 32
#define A_LD 40
#define ASMEM (2 * 3 * 128 * A_LD * 2)
__global__ void __launch_bounds__(256, 2) gemm_xg_kernel() {
    extern __shared__ __half smh[];
    __half* As = smh;                     // [3][128][40]
    __half* Bs = smh + 3 * 128 * A_LD;    // [3][128][40]
    const int tid = threadIdx.x;
    const int wid = tid >> 5;
    const int wm = wid & 3, wn = wid >> 2;
    const int tm = blockIdx.y * 128;
    const int tn = blockIdx.x * 128;

    if (blockIdx.x == 0 && blockIdx.y == 0 && tid < 16) g_cnt16[tid] = 8;  // h(0) published

    wmma::fragment<wmma::accumulator, 16, 16, 16, float> acc[2][4];
    #pragma unroll
    for (int i = 0; i < 2; i++)
        #pragma unroll
        for (int j = 0; j < 4; j++) wmma::fill_fragment(acc[i][j], 0.0f);

    auto issue = [&](int kt) {
        int st = kt % 3;
        int kk = kt * BK;
        __half* a = As + st * 128 * A_LD;
        __half* b = Bs + st * 128 * A_LD;
        #pragma unroll
        for (int i = 0; i < 4; i++) {
            int li = tid + i * 256;
            int half_sel = li >> 9;
            int lj = li & 511;
            int r = lj >> 2, sg = lj & 3;
            if (half_sel == 0)
                cp16(a + r * A_LD + sg * 8, g_xh  + (size_t)(tm + r) * HID + kk + sg * 8);
            else
                cp16(b + r * A_LD + sg * 8, g_wxh + (size_t)(tn + r) * HID + kk + sg * 8);
        }
    };
    issue(0); cp_commit();
    issue(1); cp_commit();

    for (int kt = 0; kt < HID / BK; kt++) {
        cp_wait<1>();
        __syncthreads();
        const int st = kt % 3;
        const __half* a = As + st * 128 * A_LD;
        const __half* b = Bs + st * 128 * A_LD;
        #pragma unroll
        for (int ks = 0; ks < 2; ks++) {
            wmma::fragment<wmma::matrix_a, 16, 16, 16, __half, wmma::row_major> af[2];
            wmma::fragment<wmma::matrix_b, 16, 16, 16, __half, wmma::col_major> bf[4];
            #pragma unroll
            for (int i = 0; i < 2; i++)
                wmma::load_matrix_sync(af[i], a + (wm * 32 + i * 16) * A_LD + ks * 16, A_LD);
            #pragma unroll
            for (int j = 0; j < 4; j++)
                wmma::load_matrix_sync(bf[j], b + (wn * 64 + j * 16) * A_LD + ks * 16, A_LD);
            #pragma unroll
            for (int i = 0; i < 2; i++)
                #pragma unroll
                for (int j = 0; j < 4; j++)
                    wmma::mma_sync(acc[i][j], af[i], bf[j], acc[i][j]);
        }
        if (kt + 2 < HID / BK) issue(kt + 2);
        cp_commit();
    }
    #pragma unroll
    for (int i = 0; i < 2; i++)
        #pragma unroll
        for (int j = 0; j < 4; j++) {
            size_t r = tm + wm * 32 + i * 16;
            size_t n = tn + wn * 64 + j * 16;
            wmma::store_matrix_sync(g_xg + r * NGATE + n, acc[i][j], NGATE, wmma::mem_row_major);
        }
}

// ------------------------------------------------------------------ phase B
// 2 batch groups x 64 channel blocks; h chunks arrive via cp.async.bulk (UBLKCP).
#define BSMEM (32 + 64 * WHH_LD * 2 + 6 * CHB_BYTES + (2 * 32 * 68 + 16 * 33 + 64 + 48) * 4)
__global__ void __launch_bounds__(512, 1) lstm_kernel(const float* __restrict__ c0,
                                                      const float* __restrict__ bx,
                                                      const float* __restrict__ bh,
                                                      const float* __restrict__ peep,
                                                      const float* __restrict__ bgate,
                                                      float* __restrict__ out) {
    extern __shared__ char smc[];
    uint64_t* mbar = (uint64_t*)smc;              // 3 mbarriers (24B, pad to 32)
    __half* Whs = (__half*)(smc + 32);            // [64][1032]
    __half* hAs = Whs + 64 * WHH_LD;              // [6][32][136] (3 stages x 2 K-halves)
    float*  hgS = (float*)(hAs + 6 * CHB);        // [2][32][68]
    float*  cS  = hgS + 2 * 32 * 68;              // [16][33]
    float*  cb  = cS + 16 * 33;                   // [64]
    float*  ps  = cb + 64;                        // [48]
    const uint32_t mbar0 = (uint32_t)__cvta_generic_to_shared(mbar);
    const uint32_t hAs0  = (uint32_t)__cvta_generic_to_shared(hAs);

    const int tid = threadIdx.x;
    const int wid = tid >> 5;
    const int kh  = wid >> 3;                     // K-half 0/1
    const int w8  = wid & 7;
    const int mt  = w8 & 1, nt = w8 >> 1;         // M tile 0..1, N tile 0..3
    const int j   = blockIdx.x & 63;              // channel block
    const int bg  = blockIdx.x >> 6;              // batch group
    const int c0ch = j * 16;
    const int grp = bg * 8 + (j >> 3);

    // one-time: stage this CTA's fp16 Wh slice (64 rows x 1024)
    #pragma unroll
    for (int i = 0; i < 16; i++) {
        int li = tid + i * 512;
        int n = li >> 7, sg = li & 127;
        int g = n >> 4, ch = n & 15;
        cp16(Whs + n * WHH_LD + sg * 8,
             g_whh + ((size_t)(g * HID + c0ch + ch)) * HID + sg * 8);
    }
    cp_commit();
    if (tid < 64) {
        int g = tid >> 4, ch = tid & 15;
        cb[tid] = bx[g * HID + c0ch + ch] + bh[g * HID + c0ch + ch] + bgate[g * HID + c0ch + ch];
    }
    if (tid < 48) ps[tid] = peep[(tid >> 4) * HID + c0ch + (tid & 15)];
    {
        int b = tid >> 4, ch = tid & 15;
        cS[ch * 33 + b] = c0[(size_t)(bg * MB + b) * HID + c0ch + ch];
    }
    if (tid == 0) {
        mbar_init(mbar0, 1);
        mbar_init(mbar0 + 8, 1);
        mbar_init(mbar0 + 16, 1);
        asm volatile("fence.proxy.async.shared::cta;" ::: "memory");
    }
    cp_wait<0>();
    __syncthreads();

    const int b  = tid >> 4;
    const int ch = tid & 15;
    const size_t gb = (size_t)(bg * MB + b);

    for (int t = 0; t < SEQ; t++) {
        // prefetch this step's input-gate preactivations (independent of h_t)
        const float* xr = g_xg + (gb * SEQ + t) * NGATE + c0ch + ch;
        float xi0 = __ldg(xr);
        float xi1 = __ldg(xr + HID);
        float xi2 = __ldg(xr + 2 * HID);
        float xi3 = __ldg(xr + 3 * HID);

        // tid0 polls this batch group's 8 counters with backoff, then acquires
        if (tid == 0) {
            const int need = 8 * (t + 1);
            const int* cnt = g_cnt16 + bg * 8;
            while (true) {
                int m = ld_relaxed(cnt);
                #pragma unroll
                for (int q = 1; q < 8; q++) { int v = ld_relaxed(cnt + q); m = v < m ? v : m; }
                if (m >= need) break;
                __nanosleep(64);
            }
            asm volatile("fence.acq_rel.gpu;" ::: "memory");
            asm volatile("fence.proxy.async;" ::: "memory");   // make acquired data visible to bulk engine
        }
        __syncthreads();

        const __half* hsrc = g_h2[t & 3] + (size_t)bg * 8 * CHB;
        // group q: chunk q (K-half 0) + chunk 4+q (K-half 1), one mbarrier, 2 bulk ops
        auto issueG = [&](int q) {
            int s = q % 3;
            mbar_expect_tx(mbar0 + s * 8, 2 * CHB_BYTES);
            bulk_ld(hAs0 + s * CHB_BYTES,       hsrc + q * CHB,       CHB_BYTES, mbar0 + s * 8);
            bulk_ld(hAs0 + (3 + s) * CHB_BYTES, hsrc + (4 + q) * CHB, CHB_BYTES, mbar0 + s * 8);
        };
        if (tid == 0) { issueG(0); issueG(1); }

        wmma::fragment<wmma::accumulator, 16, 16, 16, float> acc0, acc1;
        wmma::fill_fragment(acc0, 0.0f);
        wmma::fill_fragment(acc1, 0.0f);

        const int tp = t & 1;
        #pragma unroll
        for (int it = 0; it < 4; it++) {
            const int s = it & 3;  // stage pattern: 0,1,2,0
            const int stage = (it == 3) ? 0 : it;
            const int parity = (it == 0) ? 0 : (it == 3) ? 1 : tp;
            mbar_wait(mbar0 + stage * 8, parity);
            __syncthreads();
            if (tid == 0 && it < 2) issueG(it + 2);
            const __half* a = hAs + (kh * 3 + (it % 3)) * CHB;
            const int kcol = (kh * 4 + it) * 128;
            #pragma unroll
            for (int ks = 0; ks < 8; ks++) {
                wmma::fragment<wmma::matrix_a, 16, 16, 16, __half, wmma::row_major> af;
                wmma::fragment<wmma::matrix_b, 16, 16, 16, __half, wmma::col_major> bf;
                wmma::load_matrix_sync(af, a + (mt * 16) * HA_LD + ks * 16, HA_LD);
                wmma::load_matrix_sync(bf, Whs + (nt * 16) * WHH_LD + kcol + ks * 16, WHH_LD);
                if (ks & 1) wmma::mma_sync(acc1, af, bf, acc1);
                else        wmma::mma_sync(acc0, af, bf, acc0);
            }
            (void)s;
        }
        #pragma unroll
        for (int e = 0; e < acc0.num_elements; e++) acc0.x[e] += acc1.x[e];
        wmma::store_matrix_sync(hgS + kh * (32 * 68) + (mt * 16) * 68 + nt * 16,
                                acc0, 68, wmma::mem_row_major);
        __syncthreads();

        // epilogue: sum K-half partials, gates; h written into padded ring layout
        float c  = cS[ch * 33 + b];
        float h0v = hgS[b * 68 +      ch] + hgS[32 * 68 + b * 68 +      ch];
        float h1v = hgS[b * 68 + 16 + ch] + hgS[32 * 68 + b * 68 + 16 + ch];
        float h2v = hgS[b * 68 + 32 + ch] + hgS[32 * 68 + b * 68 + 32 + ch];
        float h3v = hgS[b * 68 + 48 + ch] + hgS[32 * 68 + b * 68 + 48 + ch];
        float pi = xi0 + h0v + ps[ch]      * c + cb[ch];
        float pf = xi1 + h1v + ps[16 + ch] * c + cb[16 + ch];
        float pc = xi2 + h2v                   + cb[32 + ch];
        float po = xi3 + h3v                   + cb[48 + ch];
        float cn = sigm(pf) * c + sigm(pi) + tanhf(pc);
        float hn = sigm(po + ps[32 + ch] * cn) * tanhf(cn);
        cS[ch * 33 + b] = cn;
        g_h2[(t + 1) & 3][((size_t)bg * 8 + (j >> 3)) * CHB + b * HA_LD + (j & 7) * 16 + ch]
            = __float2half(hn);
        __syncthreads();                    // all h stores happen-before the release
        if (tid == 0)
            asm volatile("red.release.gpu.global.add.s32 [%0], %1;"
                         :: "l"(g_cnt16 + grp), "r"(1) : "memory");

        // out store AFTER release — off the critical handshake path
        out[(gb * SEQ + t) * HID + c0ch + ch] = hn;
    }
}

extern "C" void kernel_launch(void* const* d_in, const int* in_sizes, int n_in,
                              void* d_out, int out_size) {
    const float* x     = (const float*)d_in[0];
    const float* h0    = (const float*)d_in[1];
    const float* c0    = (const float*)d_in[2];
    const float* Wx    = (const float*)d_in[3];
    const float* bx    = (const float*)d_in[4];
    const float* Wh    = (const float*)d_in[5];
    const float* bh    = (const float*)d_in[6];
    const float* peep  = (const float*)d_in[7];
    const float* bgate = (const float*)d_in[8];
    float* out = (float*)d_out;

    cudaFuncSetAttribute(gemm_xg_kernel, cudaFuncAttributeMaxDynamicSharedMemorySize, ASMEM);
    cudaFuncSetAttribute(lstm_kernel, cudaFuncAttributeMaxDynamicSharedMemorySize, BSMEM);

    convert_kernel<<<1024, 256>>>(x, Wx, Wh, h0);
    gemm_xg_kernel<<<dim3(32, 128), 256, ASMEM>>>();
    lstm_kernel<<<NCTA, 512, BSMEM>>>(c0, bx, bh, peep, bgate, out);
}